// round 1
// baseline (speedup 1.0000x reference)
#include <cuda_runtime.h>
#include <cuda_bf16.h>
#include <math.h>

// Problem constants (match reference setup_inputs)
#define NN    50000
#define EE    800000
#define INF_  128
#define HID   64
#define OUTC  128
#define HEADS 4
#define SLOPE 0.2f

// ---------------- static device scratch (no allocs allowed) ----------------
__device__ float g_h1  [NN * HEADS * HID];   // 50000*256  (x @ W1)
__device__ float g_out1[NN * HEADS * HID];   // layer1 aggregated output (then relu)
__device__ float g_as1 [NN * HEADS];
__device__ float g_ad1 [NN * HEADS];
__device__ float g_s1  [NN * HEADS];         // softmax denominators
__device__ float g_h2  [NN * OUTC];          // out1 @ W2
__device__ float g_as2 [NN];
__device__ float g_ad2 [NN];
__device__ float g_s2  [NN];

// ---------------- helpers ----------------
__device__ __forceinline__ float lrelu(float x) { return x >= 0.f ? x : SLOPE * x; }

__device__ __forceinline__ void red_add_v4(float* p, float4 v) {
    asm volatile("red.global.add.v4.f32 [%0], {%1,%2,%3,%4};"
                 :: "l"(p), "f"(v.x), "f"(v.y), "f"(v.z), "f"(v.w) : "memory");
}

// ---------------- zero ----------------
__global__ void zero4_kernel(float4* p, int n4) {
    int i = blockIdx.x * blockDim.x + threadIdx.x;
    if (i < n4) p[i] = make_float4(0.f, 0.f, 0.f, 0.f);
}

// ---------------- fp32 tiled GEMM: C[M,N] = A[M,K] * B[K,N] ----------------
// BM=128, BN=64, BK=16, 256 threads, 8x4 per thread. N,K multiples of 16/64.
#define GBM 128
#define GBN 64
#define GBK 16
__global__ __launch_bounds__(256) void sgemm_kernel(
    const float* __restrict__ A, const float* __restrict__ B,
    float* __restrict__ C, int M, int N, int K)
{
    __shared__ float As[GBK][GBM];
    __shared__ float Bs[GBK][GBN];
    int tid  = threadIdx.x;
    int bm   = blockIdx.y * GBM;
    int bn   = blockIdx.x * GBN;
    int trow = tid >> 4;   // 0..15 -> 8 rows each
    int tcol = tid & 15;   // 0..15 -> 4 cols each

    float acc[8][4];
#pragma unroll
    for (int i = 0; i < 8; i++)
#pragma unroll
        for (int j = 0; j < 4; j++) acc[i][j] = 0.f;

    for (int k0 = 0; k0 < K; k0 += GBK) {
        // load A tile: 128x16 = 512 float4, 2 per thread
#pragma unroll
        for (int t = 0; t < 2; t++) {
            int f = tid + t * 256;
            int r = f >> 2;
            int kc = (f & 3) * 4;
            float4 v = make_float4(0.f, 0.f, 0.f, 0.f);
            int grow = bm + r;
            if (grow < M) v = *(const float4*)(A + (long)grow * K + k0 + kc);
            As[kc + 0][r] = v.x; As[kc + 1][r] = v.y;
            As[kc + 2][r] = v.z; As[kc + 3][r] = v.w;
        }
        // load B tile: 16x64 = 256 float4, 1 per thread
        {
            int r = tid >> 4;
            int c = (tid & 15) * 4;
            float4 v = *(const float4*)(B + (long)(k0 + r) * N + bn + c);
            *(float4*)&Bs[r][c] = v;
        }
        __syncthreads();
#pragma unroll
        for (int k = 0; k < GBK; k++) {
            float am[8], bv[4];
#pragma unroll
            for (int i = 0; i < 8; i++) am[i] = As[k][trow * 8 + i];
#pragma unroll
            for (int j = 0; j < 4; j++) bv[j] = Bs[k][tcol * 4 + j];
#pragma unroll
            for (int i = 0; i < 8; i++)
#pragma unroll
                for (int j = 0; j < 4; j++)
                    acc[i][j] = fmaf(am[i], bv[j], acc[i][j]);
        }
        __syncthreads();
    }
#pragma unroll
    for (int i = 0; i < 8; i++) {
        int row = bm + trow * 8 + i;
        if (row < M) {
            float4 v = make_float4(acc[i][0], acc[i][1], acc[i][2], acc[i][3]);
            *(float4*)(C + (long)row * N + bn + tcol * 4) = v;
        }
    }
}

// ---------------- layer1 attention coefficients: thread per (node, head) ----
__global__ void attn_coef_l1(const float* __restrict__ h,
                             const float* __restrict__ a_src,
                             const float* __restrict__ a_dst,
                             float* __restrict__ as_, float* __restrict__ ad_, int n)
{
    int t = blockIdx.x * blockDim.x + threadIdx.x;
    if (t >= n * HEADS) return;
    int node = t >> 2, hd = t & 3;
    const float4* hp = (const float4*)(h + (long)node * (HEADS * HID) + hd * HID);
    const float4* sp = (const float4*)(a_src + hd * HID);
    const float4* dp = (const float4*)(a_dst + hd * HID);
    float s = 0.f, d = 0.f;
#pragma unroll
    for (int i = 0; i < HID / 4; i++) {
        float4 v = hp[i], a = sp[i], b = dp[i];
        s += v.x * a.x + v.y * a.y + v.z * a.z + v.w * a.w;
        d += v.x * b.x + v.y * b.y + v.z * b.z + v.w * b.w;
    }
    as_[t] = s;
    ad_[t] = d;
}

// ---------------- layer1 softmax denominators: thread per edge --------------
__global__ void softmax_sum_l1(const int* __restrict__ ei, int E, int Etot,
                               const float* __restrict__ as_,
                               const float* __restrict__ ad_,
                               float* __restrict__ ssum)
{
    int e = blockIdx.x * blockDim.x + threadIdx.x;
    if (e >= Etot) return;
    int s, d;
    if (e < E) { s = ei[e]; d = ei[E + e]; } else { s = e - E; d = s; }
    float4 av = *(const float4*)(as_ + s * 4);
    float4 dv = *(const float4*)(ad_ + d * 4);
    float4 ex;
    ex.x = __expf(lrelu(av.x + dv.x));
    ex.y = __expf(lrelu(av.y + dv.y));
    ex.z = __expf(lrelu(av.z + dv.z));
    ex.w = __expf(lrelu(av.w + dv.w));
    red_add_v4(ssum + d * 4, ex);
}

// ---------------- layer1 aggregate: warp per edge ---------------------------
__global__ __launch_bounds__(256) void aggregate_l1(
    const int* __restrict__ ei, int E, int Etot,
    const float* __restrict__ as_, const float* __restrict__ ad_,
    const float* __restrict__ ssum,
    const float* __restrict__ h, float* __restrict__ out)
{
    int gw = (blockIdx.x * blockDim.x + threadIdx.x) >> 5;
    int lane = threadIdx.x & 31;
    if (gw >= Etot) return;
    int s, d;
    if (gw < E) { s = ei[gw]; d = ei[E + gw]; } else { s = gw - E; d = s; }

    float w = 0.f;
    if (lane < 4) {
        float l = as_[s * 4 + lane] + ad_[d * 4 + lane];
        l = lrelu(l);
        w = __expf(l) / (ssum[d * 4 + lane] + 1e-16f);
    }
    float w0 = __shfl_sync(0xffffffffu, w, 0);
    float w1 = __shfl_sync(0xffffffffu, w, 1);
    float w2 = __shfl_sync(0xffffffffu, w, 2);
    float w3 = __shfl_sync(0xffffffffu, w, 3);

    const float4* hp = (const float4*)(h + (long)s * 256);
    float*        op = out + (long)d * 256;

    // float4 index j = lane covers heads 0..1, j = lane+32 covers heads 2..3
    float wa = (lane < 16) ? w0 : w1;
    float wb = (lane < 16) ? w2 : w3;
    float4 v = hp[lane];
    v.x *= wa; v.y *= wa; v.z *= wa; v.w *= wa;
    red_add_v4(op + lane * 4, v);
    float4 u = hp[lane + 32];
    u.x *= wb; u.y *= wb; u.z *= wb; u.w *= wb;
    red_add_v4(op + 128 + lane * 4, u);
}

// ---------------- bias + relu (in place, float4) ----------------------------
__global__ void bias_relu_kernel(float4* __restrict__ p, const float4* __restrict__ b4,
                                 int n4, int cmask4)
{
    int i = blockIdx.x * blockDim.x + threadIdx.x;
    if (i >= n4) return;
    float4 v = p[i];
    float4 b = b4[i & cmask4];
    v.x = fmaxf(v.x + b.x, 0.f);
    v.y = fmaxf(v.y + b.y, 0.f);
    v.z = fmaxf(v.z + b.z, 0.f);
    v.w = fmaxf(v.w + b.w, 0.f);
    p[i] = v;
}

// ---------------- layer2 attention coefficients: warp per node --------------
__global__ void attn_coef_l2(const float* __restrict__ h,
                             const float* __restrict__ a_src,
                             const float* __restrict__ a_dst,
                             float* __restrict__ as_, float* __restrict__ ad_, int n)
{
    int gw = (blockIdx.x * blockDim.x + threadIdx.x) >> 5;
    int lane = threadIdx.x & 31;
    if (gw >= n) return;
    float4 v = ((const float4*)(h + (long)gw * OUTC))[lane];
    float4 a = ((const float4*)a_src)[lane];
    float4 b = ((const float4*)a_dst)[lane];
    float s = v.x * a.x + v.y * a.y + v.z * a.z + v.w * a.w;
    float d = v.x * b.x + v.y * b.y + v.z * b.z + v.w * b.w;
#pragma unroll
    for (int off = 16; off; off >>= 1) {
        s += __shfl_xor_sync(0xffffffffu, s, off);
        d += __shfl_xor_sync(0xffffffffu, d, off);
    }
    if (lane == 0) { as_[gw] = s; ad_[gw] = d; }
}

// ---------------- layer2 softmax denominators -------------------------------
__global__ void softmax_sum_l2(const int* __restrict__ ei, int E, int Etot,
                               const float* __restrict__ as_,
                               const float* __restrict__ ad_,
                               float* __restrict__ ssum)
{
    int e = blockIdx.x * blockDim.x + threadIdx.x;
    if (e >= Etot) return;
    int s, d;
    if (e < E) { s = ei[e]; d = ei[E + e]; } else { s = e - E; d = s; }
    float l = lrelu(as_[s] + ad_[d]);
    atomicAdd(ssum + d, __expf(l));
}

// ---------------- layer2 aggregate: warp per edge ---------------------------
__global__ __launch_bounds__(256) void aggregate_l2(
    const int* __restrict__ ei, int E, int Etot,
    const float* __restrict__ as_, const float* __restrict__ ad_,
    const float* __restrict__ ssum,
    const float* __restrict__ h, float* __restrict__ out)
{
    int gw = (blockIdx.x * blockDim.x + threadIdx.x) >> 5;
    int lane = threadIdx.x & 31;
    if (gw >= Etot) return;
    int s, d;
    if (gw < E) { s = ei[gw]; d = ei[E + gw]; } else { s = gw - E; d = s; }
    float l = lrelu(as_[s] + ad_[d]);           // same addr across warp -> broadcast
    float w = __expf(l) / (ssum[d] + 1e-16f);
    float4 v = ((const float4*)(h + (long)s * OUTC))[lane];
    v.x *= w; v.y *= w; v.z *= w; v.w *= w;
    red_add_v4(out + (long)d * OUTC + lane * 4, v);
}

// ---------------- final bias add --------------------------------------------
__global__ void bias_add_kernel(float4* __restrict__ p, const float4* __restrict__ b4,
                                int n4, int cmask4)
{
    int i = blockIdx.x * blockDim.x + threadIdx.x;
    if (i >= n4) return;
    float4 v = p[i];
    float4 b = b4[i & cmask4];
    v.x += b.x; v.y += b.y; v.z += b.z; v.w += b.w;
    p[i] = v;
}

// ============================================================================
extern "C" void kernel_launch(void* const* d_in, const int* in_sizes, int n_in,
                              void* d_out, int out_size)
{
    const float* x      = (const float*)d_in[0];
    const int*   ei     = (const int*)  d_in[1];
    const float* W1     = (const float*)d_in[2];
    const float* a_src1 = (const float*)d_in[3];
    const float* a_dst1 = (const float*)d_in[4];
    const float* b1     = (const float*)d_in[5];
    const float* W2     = (const float*)d_in[6];
    const float* a_src2 = (const float*)d_in[7];
    const float* a_dst2 = (const float*)d_in[8];
    const float* b2     = (const float*)d_in[9];
    float* out = (float*)d_out;

    int n    = in_sizes[0] / INF_;   // 50000
    int E    = in_sizes[1] / 2;      // 800000
    int Etot = E + n;                // + self loops

    float *h1, *out1, *as1, *ad1, *s1, *h2, *as2, *ad2, *s2;
    cudaGetSymbolAddress((void**)&h1,  g_h1);
    cudaGetSymbolAddress((void**)&out1,g_out1);
    cudaGetSymbolAddress((void**)&as1, g_as1);
    cudaGetSymbolAddress((void**)&ad1, g_ad1);
    cudaGetSymbolAddress((void**)&s1,  g_s1);
    cudaGetSymbolAddress((void**)&h2,  g_h2);
    cudaGetSymbolAddress((void**)&as2, g_as2);
    cudaGetSymbolAddress((void**)&ad2, g_ad2);
    cudaGetSymbolAddress((void**)&s2,  g_s2);

    const int T = 256;
    auto cdiv = [](int a, int b) { return (a + b - 1) / b; };

    // zero accumulators
    {
        int n4 = n * 256 / 4;
        zero4_kernel<<<cdiv(n4, T), T>>>((float4*)out1, n4);
        n4 = n * HEADS / 4;
        zero4_kernel<<<cdiv(n4, T), T>>>((float4*)s1, n4);
        n4 = n / 4;
        zero4_kernel<<<cdiv(n4, T), T>>>((float4*)s2, n4);
        n4 = n * OUTC / 4;
        zero4_kernel<<<cdiv(n4, T), T>>>((float4*)out, n4);
    }

    // ---- layer 1 ----
    {
        dim3 grid(cdiv(HEADS * HID, GBN), cdiv(n, GBM));
        sgemm_kernel<<<grid, 256>>>(x, W1, h1, n, HEADS * HID, INF_);
    }
    attn_coef_l1<<<cdiv(n * HEADS, T), T>>>(h1, a_src1, a_dst1, as1, ad1, n);
    softmax_sum_l1<<<cdiv(Etot, T), T>>>(ei, E, Etot, as1, ad1, s1);
    aggregate_l1<<<cdiv(Etot * 32, T), T>>>(ei, E, Etot, as1, ad1, s1, h1, out1);
    {
        int n4 = n * 256 / 4;
        bias_relu_kernel<<<cdiv(n4, T), T>>>((float4*)out1, (const float4*)b1, n4, 63);
    }

    // ---- layer 2 ----
    {
        dim3 grid(cdiv(OUTC, GBN), cdiv(n, GBM));
        sgemm_kernel<<<grid, 256>>>(out1, W2, h2, n, OUTC, HEADS * HID);
    }
    attn_coef_l2<<<cdiv(n * 32, T), T>>>(h2, a_src2, a_dst2, as2, ad2, n);
    softmax_sum_l2<<<cdiv(Etot, T), T>>>(ei, E, Etot, as2, ad2, s2);
    aggregate_l2<<<cdiv(Etot * 32, T), T>>>(ei, E, Etot, as2, ad2, s2, h2, out);
    {
        int n4 = n * OUTC / 4;
        bias_add_kernel<<<cdiv(n4, T), T>>>((float4*)out, (const float4*)b2, n4, 31);
    }
}

// round 2
// speedup vs baseline: 1.5767x; 1.5767x over previous
#include <cuda_runtime.h>
#include <cuda_bf16.h>
#include <cstdint>
#include <math.h>

// Problem constants (match reference setup_inputs)
#define NN    50000
#define EE    800000
#define INF_  128
#define HID   64
#define OUTC  128
#define HEADS 4
#define SLOPE 0.2f

#define ETOT (EE + NN)

// ---------------- static device scratch (no allocs allowed) ----------------
__device__ float g_h1  [NN * HEADS * HID];   // x @ W1
__device__ float g_out1[NN * HEADS * HID];   // relu(aggregate + b1)
__device__ float g_as1 [NN * HEADS];
__device__ float g_ad1 [NN * HEADS];
__device__ float g_h2  [NN * OUTC];          // out1 @ W2
__device__ float g_as2 [NN];
__device__ float g_ad2 [NN];

__device__ int   g_cnt [NN];                 // degree counts / scatter cursor
__device__ int   g_off [NN + 1];             // CSR row offsets (by dst)
__device__ int   g_part[64];                 // scan partials
__device__ int   g_csr [ETOT];               // src node per CSR-sorted edge

// ---------------- helpers ----------------
__device__ __forceinline__ float lrelu(float x) { return x >= 0.f ? x : SLOPE * x; }

__device__ __forceinline__ uint32_t f2tf(float f) {
    uint32_t r;
    asm("cvt.rna.tf32.f32 %0, %1;" : "=r"(r) : "f"(f));
    return r;
}

#define MMA_TF32(c, a0, a1, a2, a3, b0, b1)                                  \
    asm volatile("mma.sync.aligned.m16n8k8.row.col.f32.tf32.tf32.f32 "       \
                 "{%0,%1,%2,%3}, {%4,%5,%6,%7}, {%8,%9}, {%0,%1,%2,%3};"     \
                 : "+f"(c[0]), "+f"(c[1]), "+f"(c[2]), "+f"(c[3])            \
                 : "r"(a0), "r"(a1), "r"(a2), "r"(a3), "r"(b0), "r"(b1))

// ============================================================================
// CSR build
// ============================================================================
__global__ void zero_int_kernel(int* p, int n) {
    int i = blockIdx.x * blockDim.x + threadIdx.x;
    if (i < n) p[i] = 0;
}

__global__ void count_kernel(const int* __restrict__ ei, int E, int Etot,
                             int* __restrict__ cnt) {
    int e = blockIdx.x * blockDim.x + threadIdx.x;
    if (e >= Etot) return;
    int d = (e < E) ? ei[E + e] : (e - E);
    atomicAdd(cnt + d, 1);
}

// block-wise inclusive scan (1024 threads/block)
__global__ void scan1_kernel(const int* __restrict__ cnt, int* __restrict__ off,
                             int* __restrict__ part, int n) {
    __shared__ int wsum[32];
    int tid = threadIdx.x;
    int i = blockIdx.x * 1024 + tid;
    int lane = tid & 31, w = tid >> 5;
    int v = (i < n) ? cnt[i] : 0;
    int x = v;
#pragma unroll
    for (int o = 1; o < 32; o <<= 1) {
        int y = __shfl_up_sync(0xffffffffu, x, o);
        if (lane >= o) x += y;
    }
    if (lane == 31) wsum[w] = x;
    __syncthreads();
    if (w == 0) {
        int s = wsum[lane];
#pragma unroll
        for (int o = 1; o < 32; o <<= 1) {
            int y = __shfl_up_sync(0xffffffffu, s, o);
            if (lane >= o) s += y;
        }
        wsum[lane] = s;
    }
    __syncthreads();
    int incl = x + (w > 0 ? wsum[w - 1] : 0);
    if (i < n) off[i + 1] = incl;
    if (tid == 1023) part[blockIdx.x] = incl;
}

// exclusive scan of <=64 partials, single block of 64 threads
__global__ void scan2_kernel(int* part, int nb) {
    __shared__ int t0;
    int tid = threadIdx.x;
    int lane = tid & 31, w = tid >> 5;
    int v = (tid < nb) ? part[tid] : 0;
    int x = v;
#pragma unroll
    for (int o = 1; o < 32; o <<= 1) {
        int y = __shfl_up_sync(0xffffffffu, x, o);
        if (lane >= o) x += y;
    }
    if (tid == 31) t0 = x;
    __syncthreads();
    if (w == 1) x += t0;
    if (tid < nb) part[tid] = x - v;
}

__global__ void scan3_kernel(int* __restrict__ off, const int* __restrict__ part,
                             int n) {
    int i = blockIdx.x * 1024 + threadIdx.x;
    if (i == 0) off[0] = 0;
    if (i < n) off[i + 1] += part[blockIdx.x];
}

__global__ void cursor_kernel(int* __restrict__ cnt, const int* __restrict__ off,
                              int n) {
    int i = blockIdx.x * blockDim.x + threadIdx.x;
    if (i < n) cnt[i] = off[i];
}

__global__ void scatter_kernel(const int* __restrict__ ei, int E, int Etot,
                               int* __restrict__ cur, int* __restrict__ csr) {
    int e = blockIdx.x * blockDim.x + threadIdx.x;
    if (e >= Etot) return;
    int s, d;
    if (e < E) { s = ei[e]; d = ei[E + e]; } else { s = e - E; d = s; }
    int pos = atomicAdd(cur + d, 1);
    csr[pos] = s;
}

// ============================================================================
// 3xTF32 tensor-core GEMM: C[M,N] = A[M,K] * B[K,N], fp32 in/out.
// BM=128, BN=128, BK=16, 256 threads, warp tile 64x32, mma m16n8k8.
// N multiple of 128, K multiple of 16.
// ============================================================================
#define BM 128
#define BN 128
#define BK 16
#define KST 17   // padded k-stride in elements

__global__ __launch_bounds__(256) void gemm3x_kernel(
    const float* __restrict__ A, const float* __restrict__ B,
    float* __restrict__ C, int M, int N, int K)
{
    __shared__ uint32_t Ah[BM * KST], Al[BM * KST];
    __shared__ uint32_t Bh[BN * KST], Bl[BN * KST];

    int tid  = threadIdx.x;
    int bm   = blockIdx.y * BM;
    int bn   = blockIdx.x * BN;
    int warp = tid >> 5, lane = tid & 31;
    int wm = (warp & 1) * 64;
    int wn = (warp >> 1) * 32;
    int g = lane >> 2, t = lane & 3;

    float acc[4][4][4];
#pragma unroll
    for (int mi = 0; mi < 4; mi++)
#pragma unroll
        for (int ni = 0; ni < 4; ni++)
#pragma unroll
            for (int j = 0; j < 4; j++) acc[mi][ni][j] = 0.f;

    float4 ra[2], rb[2];

    auto loadTiles = [&](int kt) {
#pragma unroll
        for (int t2 = 0; t2 < 2; t2++) {
            int f = tid + t2 * 256;
            int r = f >> 2, kc = (f & 3) * 4;
            int row = bm + r;
            ra[t2] = (row < M) ? *(const float4*)(A + (size_t)row * K + kt + kc)
                               : make_float4(0.f, 0.f, 0.f, 0.f);
        }
#pragma unroll
        for (int t2 = 0; t2 < 2; t2++) {
            int f = tid + t2 * 256;
            int kr = f >> 5, c = (f & 31) * 4;
            rb[t2] = *(const float4*)(B + (size_t)(kt + kr) * N + bn + c);
        }
    };

    auto storeTiles = [&]() {
#pragma unroll
        for (int t2 = 0; t2 < 2; t2++) {
            int f = tid + t2 * 256;
            int r = f >> 2, kc = (f & 3) * 4;
            float vv[4] = {ra[t2].x, ra[t2].y, ra[t2].z, ra[t2].w};
#pragma unroll
            for (int j = 0; j < 4; j++) {
                uint32_t hi = f2tf(vv[j]);
                uint32_t lo = f2tf(vv[j] - __uint_as_float(hi));
                Ah[r * KST + kc + j] = hi;
                Al[r * KST + kc + j] = lo;
            }
        }
#pragma unroll
        for (int t2 = 0; t2 < 2; t2++) {
            int f = tid + t2 * 256;
            int kr = f >> 5, c = (f & 31) * 4;
            float vv[4] = {rb[t2].x, rb[t2].y, rb[t2].z, rb[t2].w};
#pragma unroll
            for (int j = 0; j < 4; j++) {
                uint32_t hi = f2tf(vv[j]);
                uint32_t lo = f2tf(vv[j] - __uint_as_float(hi));
                Bh[(c + j) * KST + kr] = hi;
                Bl[(c + j) * KST + kr] = lo;
            }
        }
    };

    loadTiles(0);
    storeTiles();
    __syncthreads();

    for (int kt = 0; kt < K; kt += BK) {
        bool nx = (kt + BK) < K;
        if (nx) loadTiles(kt + BK);

#pragma unroll
        for (int kc = 0; kc < 2; kc++) {
            int k0 = kc * 8;
            uint32_t bh[4][2], bl[4][2];
#pragma unroll
            for (int ni = 0; ni < 4; ni++) {
                int col = (wn + ni * 8 + g) * KST;
                bh[ni][0] = Bh[col + k0 + t];
                bh[ni][1] = Bh[col + k0 + 4 + t];
                bl[ni][0] = Bl[col + k0 + t];
                bl[ni][1] = Bl[col + k0 + 4 + t];
            }
#pragma unroll
            for (int mi = 0; mi < 4; mi++) {
                int r0 = (wm + mi * 16 + g) * KST;
                int r1 = (wm + mi * 16 + 8 + g) * KST;
                uint32_t ah0 = Ah[r0 + k0 + t],     ah1 = Ah[r1 + k0 + t];
                uint32_t ah2 = Ah[r0 + k0 + 4 + t], ah3 = Ah[r1 + k0 + 4 + t];
                uint32_t al0 = Al[r0 + k0 + t],     al1 = Al[r1 + k0 + t];
                uint32_t al2 = Al[r0 + k0 + 4 + t], al3 = Al[r1 + k0 + 4 + t];
#pragma unroll
                for (int ni = 0; ni < 4; ni++) {
                    MMA_TF32(acc[mi][ni], ah0, ah1, ah2, ah3, bh[ni][0], bh[ni][1]);
                    MMA_TF32(acc[mi][ni], ah0, ah1, ah2, ah3, bl[ni][0], bl[ni][1]);
                    MMA_TF32(acc[mi][ni], al0, al1, al2, al3, bh[ni][0], bh[ni][1]);
                }
            }
        }
        __syncthreads();
        if (nx) {
            storeTiles();
        }
        __syncthreads();
    }

    // epilogue
#pragma unroll
    for (int mi = 0; mi < 4; mi++) {
#pragma unroll
        for (int ni = 0; ni < 4; ni++) {
            int row = bm + wm + mi * 16 + g;
            int col = bn + wn + ni * 8 + 2 * t;
            if (row < M)
                *(float2*)(C + (size_t)row * N + col) =
                    make_float2(acc[mi][ni][0], acc[mi][ni][1]);
            if (row + 8 < M)
                *(float2*)(C + (size_t)(row + 8) * N + col) =
                    make_float2(acc[mi][ni][2], acc[mi][ni][3]);
        }
    }
}

// ============================================================================
// attention coefficients
// ============================================================================
__global__ void attn_coef_l1(const float* __restrict__ h,
                             const float* __restrict__ a_src,
                             const float* __restrict__ a_dst,
                             float* __restrict__ as_, float* __restrict__ ad_, int n)
{
    int tt = blockIdx.x * blockDim.x + threadIdx.x;
    if (tt >= n * HEADS) return;
    int node = tt >> 2, hd = tt & 3;
    const float4* hp = (const float4*)(h + (size_t)node * (HEADS * HID) + hd * HID);
    const float4* sp = (const float4*)(a_src + hd * HID);
    const float4* dp = (const float4*)(a_dst + hd * HID);
    float s = 0.f, d = 0.f;
#pragma unroll
    for (int i = 0; i < HID / 4; i++) {
        float4 v = hp[i], a = sp[i], b = dp[i];
        s += v.x * a.x + v.y * a.y + v.z * a.z + v.w * a.w;
        d += v.x * b.x + v.y * b.y + v.z * b.z + v.w * b.w;
    }
    as_[tt] = s;
    ad_[tt] = d;
}

__global__ void attn_coef_l2(const float* __restrict__ h,
                             const float* __restrict__ a_src,
                             const float* __restrict__ a_dst,
                             float* __restrict__ as_, float* __restrict__ ad_, int n)
{
    int gw = (blockIdx.x * blockDim.x + threadIdx.x) >> 5;
    int lane = threadIdx.x & 31;
    if (gw >= n) return;
    float4 v = ((const float4*)(h + (size_t)gw * OUTC))[lane];
    float4 a = ((const float4*)a_src)[lane];
    float4 b = ((const float4*)a_dst)[lane];
    float s = v.x * a.x + v.y * a.y + v.z * a.z + v.w * a.w;
    float d = v.x * b.x + v.y * b.y + v.z * b.z + v.w * b.w;
#pragma unroll
    for (int off = 16; off; off >>= 1) {
        s += __shfl_xor_sync(0xffffffffu, s, off);
        d += __shfl_xor_sync(0xffffffffu, d, off);
    }
    if (lane == 0) { as_[gw] = s; ad_[gw] = d; }
}

// ============================================================================
// layer-1 aggregation: one warp per dst node, CSR gather.
// Computes softmax denominator then weighted sum; fuses bias + relu.
// ============================================================================
__global__ __launch_bounds__(256) void aggregate_l1(
    const int* __restrict__ off, const int* __restrict__ csr,
    const float* __restrict__ as_, const float* __restrict__ ad_,
    const float* __restrict__ h, const float* __restrict__ b1,
    float* __restrict__ out, int n)
{
    int gw = (blockIdx.x * blockDim.x + threadIdx.x) >> 5;
    int lane = threadIdx.x & 31;
    if (gw >= n) return;
    int start = off[gw], end = off[gw + 1];

    float4 adv = *(const float4*)(ad_ + (size_t)gw * 4);

    // pass 1: softmax denominators (lane-parallel over edges)
    float4 ds = make_float4(0.f, 0.f, 0.f, 0.f);
    for (int e = start + lane; e < end; e += 32) {
        int s = csr[e];
        float4 av = *(const float4*)(as_ + (size_t)s * 4);
        ds.x += __expf(lrelu(av.x + adv.x));
        ds.y += __expf(lrelu(av.y + adv.y));
        ds.z += __expf(lrelu(av.z + adv.z));
        ds.w += __expf(lrelu(av.w + adv.w));
    }
#pragma unroll
    for (int o = 16; o; o >>= 1) {
        ds.x += __shfl_xor_sync(0xffffffffu, ds.x, o);
        ds.y += __shfl_xor_sync(0xffffffffu, ds.y, o);
        ds.z += __shfl_xor_sync(0xffffffffu, ds.z, o);
        ds.w += __shfl_xor_sync(0xffffffffu, ds.w, o);
    }

    // this lane covers channels [lane*4, +4) (head hA) and [128+lane*4, +4) (head hA+2)
    int hA = lane >> 4;                               // 0 or 1
    float adA = (hA == 0) ? adv.x : adv.y;
    float adB = (hA == 0) ? adv.z : adv.w;
    float rA = 1.f / (((hA == 0) ? ds.x : ds.y) + 1e-16f);
    float rB = 1.f / (((hA == 0) ? ds.z : ds.w) + 1e-16f);

    float4 acc0 = make_float4(0.f, 0.f, 0.f, 0.f);
    float4 acc1 = make_float4(0.f, 0.f, 0.f, 0.f);

    int sc = (start < end) ? csr[start] : 0;
    for (int e = start; e < end; e++) {
        int s = sc;
        if (e + 1 < end) sc = csr[e + 1];
        float asA = as_[(size_t)s * 4 + hA];
        float asB = as_[(size_t)s * 4 + 2 + hA];
        float wA = __expf(lrelu(asA + adA)) * rA;
        float wB = __expf(lrelu(asB + adB)) * rB;
        const float4* hp = (const float4*)(h + (size_t)s * 256);
        float4 v = hp[lane];
        float4 u = hp[lane + 32];
        acc0.x += v.x * wA; acc0.y += v.y * wA; acc0.z += v.z * wA; acc0.w += v.w * wA;
        acc1.x += u.x * wB; acc1.y += u.y * wB; acc1.z += u.z * wB; acc1.w += u.w * wB;
    }

    float4 bb0 = ((const float4*)b1)[lane];
    float4 bb1 = ((const float4*)b1)[lane + 32];
    acc0.x = fmaxf(acc0.x + bb0.x, 0.f); acc0.y = fmaxf(acc0.y + bb0.y, 0.f);
    acc0.z = fmaxf(acc0.z + bb0.z, 0.f); acc0.w = fmaxf(acc0.w + bb0.w, 0.f);
    acc1.x = fmaxf(acc1.x + bb1.x, 0.f); acc1.y = fmaxf(acc1.y + bb1.y, 0.f);
    acc1.z = fmaxf(acc1.z + bb1.z, 0.f); acc1.w = fmaxf(acc1.w + bb1.w, 0.f);

    float4* op = (float4*)(out + (size_t)gw * 256);
    op[lane] = acc0;
    op[lane + 32] = acc1;
}

// ============================================================================
// layer-2 aggregation: one warp per dst node, single head, fuses bias add.
// ============================================================================
__global__ __launch_bounds__(256) void aggregate_l2(
    const int* __restrict__ off, const int* __restrict__ csr,
    const float* __restrict__ as_, const float* __restrict__ ad_,
    const float* __restrict__ h, const float* __restrict__ b2,
    float* __restrict__ out, int n)
{
    int gw = (blockIdx.x * blockDim.x + threadIdx.x) >> 5;
    int lane = threadIdx.x & 31;
    if (gw >= n) return;
    int start = off[gw], end = off[gw + 1];

    float adn = ad_[gw];

    float ds = 0.f;
    for (int e = start + lane; e < end; e += 32) {
        int s = csr[e];
        ds += __expf(lrelu(as_[s] + adn));
    }
#pragma unroll
    for (int o = 16; o; o >>= 1) ds += __shfl_xor_sync(0xffffffffu, ds, o);
    float r = 1.f / (ds + 1e-16f);

    float4 acc = make_float4(0.f, 0.f, 0.f, 0.f);
    int sc = (start < end) ? csr[start] : 0;
    for (int e = start; e < end; e++) {
        int s = sc;
        if (e + 1 < end) sc = csr[e + 1];
        float w = __expf(lrelu(as_[s] + adn)) * r;
        float4 v = ((const float4*)(h + (size_t)s * OUTC))[lane];
        acc.x += v.x * w; acc.y += v.y * w; acc.z += v.z * w; acc.w += v.w * w;
    }

    float4 bb = ((const float4*)b2)[lane];
    acc.x += bb.x; acc.y += bb.y; acc.z += bb.z; acc.w += bb.w;
    ((float4*)(out + (size_t)gw * OUTC))[lane] = acc;
}

// ============================================================================
extern "C" void kernel_launch(void* const* d_in, const int* in_sizes, int n_in,
                              void* d_out, int out_size)
{
    const float* x      = (const float*)d_in[0];
    const int*   ei     = (const int*)  d_in[1];
    const float* W1     = (const float*)d_in[2];
    const float* a_src1 = (const float*)d_in[3];
    const float* a_dst1 = (const float*)d_in[4];
    const float* b1     = (const float*)d_in[5];
    const float* W2     = (const float*)d_in[6];
    const float* a_src2 = (const float*)d_in[7];
    const float* a_dst2 = (const float*)d_in[8];
    const float* b2     = (const float*)d_in[9];
    float* out = (float*)d_out;

    int n    = in_sizes[0] / INF_;   // 50000
    int E    = in_sizes[1] / 2;      // 800000
    int Etot = E + n;

    float *h1, *out1, *as1, *ad1, *h2, *as2, *ad2;
    int *cnt, *off, *part, *csr;
    cudaGetSymbolAddress((void**)&h1,  g_h1);
    cudaGetSymbolAddress((void**)&out1,g_out1);
    cudaGetSymbolAddress((void**)&as1, g_as1);
    cudaGetSymbolAddress((void**)&ad1, g_ad1);
    cudaGetSymbolAddress((void**)&h2,  g_h2);
    cudaGetSymbolAddress((void**)&as2, g_as2);
    cudaGetSymbolAddress((void**)&ad2, g_ad2);
    cudaGetSymbolAddress((void**)&cnt, g_cnt);
    cudaGetSymbolAddress((void**)&off, g_off);
    cudaGetSymbolAddress((void**)&part,g_part);
    cudaGetSymbolAddress((void**)&csr, g_csr);

    const int T = 256;
    auto cdiv = [](int a, int b) { return (a + b - 1) / b; };
    int nchunks = cdiv(n, 1024);

    // ---- CSR build (by destination) ----
    zero_int_kernel<<<cdiv(n, T), T>>>(cnt, n);
    count_kernel<<<cdiv(Etot, T), T>>>(ei, E, Etot, cnt);
    scan1_kernel<<<nchunks, 1024>>>(cnt, off, part, n);
    scan2_kernel<<<1, 64>>>(part, nchunks);
    scan3_kernel<<<nchunks, 1024>>>(off, part, n);
    cursor_kernel<<<cdiv(n, T), T>>>(cnt, off, n);
    scatter_kernel<<<cdiv(Etot, T), T>>>(ei, E, Etot, cnt, csr);

    // ---- layer 1 ----
    {
        dim3 grid(cdiv(HEADS * HID, BN), cdiv(n, BM));
        gemm3x_kernel<<<grid, 256>>>(x, W1, h1, n, HEADS * HID, INF_);
    }
    attn_coef_l1<<<cdiv(n * HEADS, T), T>>>(h1, a_src1, a_dst1, as1, ad1, n);
    aggregate_l1<<<cdiv(n * 32, T), T>>>(off, csr, as1, ad1, h1, b1, out1, n);

    // ---- layer 2 ----
    {
        dim3 grid(cdiv(OUTC, BN), cdiv(n, BM));
        gemm3x_kernel<<<grid, 256>>>(out1, W2, h2, n, OUTC, HEADS * HID);
    }
    attn_coef_l2<<<cdiv(n * 32, T), T>>>(h2, a_src2, a_dst2, as2, ad2, n);
    aggregate_l2<<<cdiv(n * 32, T), T>>>(off, csr, as2, ad2, h2, b2, out, n);
}

// round 3
// speedup vs baseline: 1.6450x; 1.0433x over previous
#include <cuda_runtime.h>
#include <cuda_bf16.h>
#include <cstdint>
#include <math.h>

// Problem constants (match reference setup_inputs)
#define NN    50000
#define EE    800000
#define INF_  128
#define HID   64
#define OUTC  128
#define HEADS 4
#define SLOPE 0.2f

#define ETOT (EE + NN)

// ---------------- static device scratch (no allocs allowed) ----------------
__device__ float g_h1  [NN * HEADS * HID];   // x @ W1
__device__ float g_out1[NN * HEADS * HID];   // relu(aggregate + b1)
__device__ float g_as1 [NN * HEADS];
__device__ float g_ad1 [NN * HEADS];
__device__ float g_h2  [NN * OUTC];          // out1 @ W2
__device__ float g_as2 [NN];
__device__ float g_ad2 [NN];

__device__ int   g_cnt [NN];                 // degree counts / scatter cursor
__device__ int   g_off [NN + 1];             // CSR row offsets (by dst)
__device__ int   g_part[64];                 // per-block totals from scan1
__device__ int   g_csr [ETOT];               // src node per CSR-sorted edge

// ---------------- helpers ----------------
__device__ __forceinline__ float lrelu(float x) { return x >= 0.f ? x : SLOPE * x; }

__device__ __forceinline__ uint32_t f2tf(float f) {
    uint32_t r;
    asm("cvt.rna.tf32.f32 %0, %1;" : "=r"(r) : "f"(f));
    return r;
}

#define MMA_TF32(c, a0, a1, a2, a3, b0, b1)                                  \
    asm volatile("mma.sync.aligned.m16n8k8.row.col.f32.tf32.tf32.f32 "       \
                 "{%0,%1,%2,%3}, {%4,%5,%6,%7}, {%8,%9}, {%0,%1,%2,%3};"     \
                 : "+f"(c[0]), "+f"(c[1]), "+f"(c[2]), "+f"(c[3])            \
                 : "r"(a0), "r"(a1), "r"(a2), "r"(a3), "r"(b0), "r"(b1))

// ============================================================================
// CSR build (4 kernels + 1 memset, runs on side stream)
// ============================================================================
__global__ void count_kernel(const int* __restrict__ ei, int E, int Etot,
                             int* __restrict__ cnt) {
    int e = blockIdx.x * blockDim.x + threadIdx.x;
    if (e >= Etot) return;
    int d = (e < E) ? ei[E + e] : (e - E);
    atomicAdd(cnt + d, 1);
}

// block-wise inclusive scan (1024 threads/block); off[i+1]=local incl, part[b]=block total
__global__ void scan1_kernel(const int* __restrict__ cnt, int* __restrict__ off,
                             int* __restrict__ part, int n) {
    __shared__ int wsum[32];
    int tid = threadIdx.x;
    int i = blockIdx.x * 1024 + tid;
    int lane = tid & 31, w = tid >> 5;
    int v = (i < n) ? cnt[i] : 0;
    int x = v;
#pragma unroll
    for (int o = 1; o < 32; o <<= 1) {
        int y = __shfl_up_sync(0xffffffffu, x, o);
        if (lane >= o) x += y;
    }
    if (lane == 31) wsum[w] = x;
    __syncthreads();
    if (w == 0) {
        int s = wsum[lane];
#pragma unroll
        for (int o = 1; o < 32; o <<= 1) {
            int y = __shfl_up_sync(0xffffffffu, s, o);
            if (lane >= o) s += y;
        }
        wsum[lane] = s;
    }
    __syncthreads();
    int incl = x + (w > 0 ? wsum[w - 1] : 0);
    if (i < n) off[i + 1] = incl;
    if (tid == 1023) part[blockIdx.x] = incl;
}

// each block computes its own base = sum(part[0..b-1]) (nb <= 64),
// finalizes off[], and initializes the scatter cursor cnt[] = off[].
__global__ void scan_fix_kernel(int* __restrict__ off, int* __restrict__ cnt,
                                const int* __restrict__ part, int n) {
    __shared__ int wsum2[2];
    __shared__ int base_s;
    int b = blockIdx.x;
    int tid = threadIdx.x;
    if (tid < 64) {
        int v = (tid < b) ? part[tid] : 0;
#pragma unroll
        for (int o = 16; o; o >>= 1) v += __shfl_xor_sync(0xffffffffu, v, o);
        if ((tid & 31) == 0) wsum2[tid >> 5] = v;
    }
    __syncthreads();
    if (tid == 0) base_s = wsum2[0] + wsum2[1];
    __syncthreads();
    int base = base_s;
    int i = b * 1024 + tid;
    if (b == 0 && tid == 0) { off[0] = 0; cnt[0] = 0; }
    if (i < n) {
        int o = off[i + 1] + base;
        off[i + 1] = o;
        if (i + 1 < n) cnt[i + 1] = o;
    }
}

__global__ void scatter_kernel(const int* __restrict__ ei, int E, int Etot,
                               int* __restrict__ cur, int* __restrict__ csr) {
    int e = blockIdx.x * blockDim.x + threadIdx.x;
    if (e >= Etot) return;
    int s, d;
    if (e < E) { s = ei[e]; d = ei[E + e]; } else { s = e - E; d = s; }
    int pos = atomicAdd(cur + d, 1);
    csr[pos] = s;
}

// ============================================================================
// 3xTF32 tensor-core GEMM: C[M,N] = A[M,K] * B[K,N], fp32 in/out.
// BM=128, BN=128, BK=16, 256 threads, warp tile 64x32, mma m16n8k8.
// N multiple of 128, K multiple of 16.
// ============================================================================
#define BM 128
#define BN 128
#define BK 16
#define KST 17   // padded k-stride in elements

__global__ __launch_bounds__(256) void gemm3x_kernel(
    const float* __restrict__ A, const float* __restrict__ B,
    float* __restrict__ C, int M, int N, int K)
{
    __shared__ uint32_t Ah[BM * KST], Al[BM * KST];
    __shared__ uint32_t Bh[BN * KST], Bl[BN * KST];

    int tid  = threadIdx.x;
    int bm   = blockIdx.y * BM;
    int bn   = blockIdx.x * BN;
    int warp = tid >> 5, lane = tid & 31;
    int wm = (warp & 1) * 64;
    int wn = (warp >> 1) * 32;
    int g = lane >> 2, t = lane & 3;

    float acc[4][4][4];
#pragma unroll
    for (int mi = 0; mi < 4; mi++)
#pragma unroll
        for (int ni = 0; ni < 4; ni++)
#pragma unroll
            for (int j = 0; j < 4; j++) acc[mi][ni][j] = 0.f;

    float4 ra[2], rb[2];

    auto loadTiles = [&](int kt) {
#pragma unroll
        for (int t2 = 0; t2 < 2; t2++) {
            int f = tid + t2 * 256;
            int r = f >> 2, kc = (f & 3) * 4;
            int row = bm + r;
            ra[t2] = (row < M) ? *(const float4*)(A + (size_t)row * K + kt + kc)
                               : make_float4(0.f, 0.f, 0.f, 0.f);
        }
#pragma unroll
        for (int t2 = 0; t2 < 2; t2++) {
            int f = tid + t2 * 256;
            int kr = f >> 5, c = (f & 31) * 4;
            rb[t2] = *(const float4*)(B + (size_t)(kt + kr) * N + bn + c);
        }
    };

    auto storeTiles = [&]() {
#pragma unroll
        for (int t2 = 0; t2 < 2; t2++) {
            int f = tid + t2 * 256;
            int r = f >> 2, kc = (f & 3) * 4;
            float vv[4] = {ra[t2].x, ra[t2].y, ra[t2].z, ra[t2].w};
#pragma unroll
            for (int j = 0; j < 4; j++) {
                uint32_t hi = f2tf(vv[j]);
                uint32_t lo = f2tf(vv[j] - __uint_as_float(hi));
                Ah[r * KST + kc + j] = hi;
                Al[r * KST + kc + j] = lo;
            }
        }
#pragma unroll
        for (int t2 = 0; t2 < 2; t2++) {
            int f = tid + t2 * 256;
            int kr = f >> 5, c = (f & 31) * 4;
            float vv[4] = {rb[t2].x, rb[t2].y, rb[t2].z, rb[t2].w};
#pragma unroll
            for (int j = 0; j < 4; j++) {
                uint32_t hi = f2tf(vv[j]);
                uint32_t lo = f2tf(vv[j] - __uint_as_float(hi));
                Bh[(c + j) * KST + kr] = hi;
                Bl[(c + j) * KST + kr] = lo;
            }
        }
    };

    loadTiles(0);
    storeTiles();
    __syncthreads();

    for (int kt = 0; kt < K; kt += BK) {
        bool nx = (kt + BK) < K;
        if (nx) loadTiles(kt + BK);

#pragma unroll
        for (int kc = 0; kc < 2; kc++) {
            int k0 = kc * 8;
            uint32_t bh[4][2], bl[4][2];
#pragma unroll
            for (int ni = 0; ni < 4; ni++) {
                int col = (wn + ni * 8 + g) * KST;
                bh[ni][0] = Bh[col + k0 + t];
                bh[ni][1] = Bh[col + k0 + 4 + t];
                bl[ni][0] = Bl[col + k0 + t];
                bl[ni][1] = Bl[col + k0 + 4 + t];
            }
#pragma unroll
            for (int mi = 0; mi < 4; mi++) {
                int r0 = (wm + mi * 16 + g) * KST;
                int r1 = (wm + mi * 16 + 8 + g) * KST;
                uint32_t ah0 = Ah[r0 + k0 + t],     ah1 = Ah[r1 + k0 + t];
                uint32_t ah2 = Ah[r0 + k0 + 4 + t], ah3 = Ah[r1 + k0 + 4 + t];
                uint32_t al0 = Al[r0 + k0 + t],     al1 = Al[r1 + k0 + t];
                uint32_t al2 = Al[r0 + k0 + 4 + t], al3 = Al[r1 + k0 + 4 + t];
#pragma unroll
                for (int ni = 0; ni < 4; ni++) {
                    MMA_TF32(acc[mi][ni], ah0, ah1, ah2, ah3, bh[ni][0], bh[ni][1]);
                    MMA_TF32(acc[mi][ni], ah0, ah1, ah2, ah3, bl[ni][0], bl[ni][1]);
                    MMA_TF32(acc[mi][ni], al0, al1, al2, al3, bh[ni][0], bh[ni][1]);
                }
            }
        }
        __syncthreads();
        if (nx) {
            storeTiles();
        }
        __syncthreads();
    }

    // epilogue
#pragma unroll
    for (int mi = 0; mi < 4; mi++) {
#pragma unroll
        for (int ni = 0; ni < 4; ni++) {
            int row = bm + wm + mi * 16 + g;
            int col = bn + wn + ni * 8 + 2 * t;
            if (row < M)
                *(float2*)(C + (size_t)row * N + col) =
                    make_float2(acc[mi][ni][0], acc[mi][ni][1]);
            if (row + 8 < M)
                *(float2*)(C + (size_t)(row + 8) * N + col) =
                    make_float2(acc[mi][ni][2], acc[mi][ni][3]);
        }
    }
}

// ============================================================================
// attention coefficients
// ============================================================================
__global__ void attn_coef_l1(const float* __restrict__ h,
                             const float* __restrict__ a_src,
                             const float* __restrict__ a_dst,
                             float* __restrict__ as_, float* __restrict__ ad_, int n)
{
    int tt = blockIdx.x * blockDim.x + threadIdx.x;
    if (tt >= n * HEADS) return;
    int node = tt >> 2, hd = tt & 3;
    const float4* hp = (const float4*)(h + (size_t)node * (HEADS * HID) + hd * HID);
    const float4* sp = (const float4*)(a_src + hd * HID);
    const float4* dp = (const float4*)(a_dst + hd * HID);
    float s = 0.f, d = 0.f;
#pragma unroll
    for (int i = 0; i < HID / 4; i++) {
        float4 v = hp[i], a = sp[i], b = dp[i];
        s += v.x * a.x + v.y * a.y + v.z * a.z + v.w * a.w;
        d += v.x * b.x + v.y * b.y + v.z * b.z + v.w * b.w;
    }
    as_[tt] = s;
    ad_[tt] = d;
}

__global__ void attn_coef_l2(const float* __restrict__ h,
                             const float* __restrict__ a_src,
                             const float* __restrict__ a_dst,
                             float* __restrict__ as_, float* __restrict__ ad_, int n)
{
    int gw = (blockIdx.x * blockDim.x + threadIdx.x) >> 5;
    int lane = threadIdx.x & 31;
    if (gw >= n) return;
    float4 v = ((const float4*)(h + (size_t)gw * OUTC))[lane];
    float4 a = ((const float4*)a_src)[lane];
    float4 b = ((const float4*)a_dst)[lane];
    float s = v.x * a.x + v.y * a.y + v.z * a.z + v.w * a.w;
    float d = v.x * b.x + v.y * b.y + v.z * b.z + v.w * b.w;
#pragma unroll
    for (int off = 16; off; off >>= 1) {
        s += __shfl_xor_sync(0xffffffffu, s, off);
        d += __shfl_xor_sync(0xffffffffu, d, off);
    }
    if (lane == 0) { as_[gw] = s; ad_[gw] = d; }
}

// ============================================================================
// layer-1 aggregation: one warp per dst node, CSR gather, 2-way edge unroll.
// Computes softmax denominator then weighted sum; fuses bias + relu.
// ============================================================================
__global__ __launch_bounds__(256) void aggregate_l1(
    const int* __restrict__ off, const int* __restrict__ csr,
    const float* __restrict__ as_, const float* __restrict__ ad_,
    const float* __restrict__ h, const float* __restrict__ b1,
    float* __restrict__ out, int n)
{
    int gw = (blockIdx.x * blockDim.x + threadIdx.x) >> 5;
    int lane = threadIdx.x & 31;
    if (gw >= n) return;
    int start = off[gw], end = off[gw + 1];

    float4 adv = *(const float4*)(ad_ + (size_t)gw * 4);

    // pass 1: softmax denominators (lane-parallel over edges)
    float4 ds = make_float4(0.f, 0.f, 0.f, 0.f);
    for (int e = start + lane; e < end; e += 32) {
        int s = csr[e];
        float4 av = *(const float4*)(as_ + (size_t)s * 4);
        ds.x += __expf(lrelu(av.x + adv.x));
        ds.y += __expf(lrelu(av.y + adv.y));
        ds.z += __expf(lrelu(av.z + adv.z));
        ds.w += __expf(lrelu(av.w + adv.w));
    }
#pragma unroll
    for (int o = 16; o; o >>= 1) {
        ds.x += __shfl_xor_sync(0xffffffffu, ds.x, o);
        ds.y += __shfl_xor_sync(0xffffffffu, ds.y, o);
        ds.z += __shfl_xor_sync(0xffffffffu, ds.z, o);
        ds.w += __shfl_xor_sync(0xffffffffu, ds.w, o);
    }

    // this lane covers channels [lane*4,+4) (head hA) and [128+lane*4,+4) (head hA+2)
    int hA = lane >> 4;
    float adA = (hA == 0) ? adv.x : adv.y;
    float adB = (hA == 0) ? adv.z : adv.w;
    float rA = 1.f / (((hA == 0) ? ds.x : ds.y) + 1e-16f);
    float rB = 1.f / (((hA == 0) ? ds.z : ds.w) + 1e-16f);

    float4 acc0 = make_float4(0.f, 0.f, 0.f, 0.f);
    float4 acc1 = make_float4(0.f, 0.f, 0.f, 0.f);

    int e = start;
    for (; e + 2 <= end; e += 2) {
        int s0 = csr[e], s1 = csr[e + 1];
        const float4* hp0 = (const float4*)(h + (size_t)s0 * 256);
        const float4* hp1 = (const float4*)(h + (size_t)s1 * 256);
        float4 v0 = hp0[lane],      v1 = hp1[lane];
        float4 u0 = hp0[lane + 32], u1 = hp1[lane + 32];
        float wA0 = __expf(lrelu(as_[(size_t)s0 * 4 + hA] + adA)) * rA;
        float wB0 = __expf(lrelu(as_[(size_t)s0 * 4 + 2 + hA] + adB)) * rB;
        float wA1 = __expf(lrelu(as_[(size_t)s1 * 4 + hA] + adA)) * rA;
        float wB1 = __expf(lrelu(as_[(size_t)s1 * 4 + 2 + hA] + adB)) * rB;
        acc0.x += v0.x * wA0 + v1.x * wA1; acc0.y += v0.y * wA0 + v1.y * wA1;
        acc0.z += v0.z * wA0 + v1.z * wA1; acc0.w += v0.w * wA0 + v1.w * wA1;
        acc1.x += u0.x * wB0 + u1.x * wB1; acc1.y += u0.y * wB0 + u1.y * wB1;
        acc1.z += u0.z * wB0 + u1.z * wB1; acc1.w += u0.w * wB0 + u1.w * wB1;
    }
    if (e < end) {
        int s0 = csr[e];
        const float4* hp0 = (const float4*)(h + (size_t)s0 * 256);
        float4 v0 = hp0[lane], u0 = hp0[lane + 32];
        float wA0 = __expf(lrelu(as_[(size_t)s0 * 4 + hA] + adA)) * rA;
        float wB0 = __expf(lrelu(as_[(size_t)s0 * 4 + 2 + hA] + adB)) * rB;
        acc0.x += v0.x * wA0; acc0.y += v0.y * wA0;
        acc0.z += v0.z * wA0; acc0.w += v0.w * wA0;
        acc1.x += u0.x * wB0; acc1.y += u0.y * wB0;
        acc1.z += u0.z * wB0; acc1.w += u0.w * wB0;
    }

    float4 bb0 = ((const float4*)b1)[lane];
    float4 bb1 = ((const float4*)b1)[lane + 32];
    acc0.x = fmaxf(acc0.x + bb0.x, 0.f); acc0.y = fmaxf(acc0.y + bb0.y, 0.f);
    acc0.z = fmaxf(acc0.z + bb0.z, 0.f); acc0.w = fmaxf(acc0.w + bb0.w, 0.f);
    acc1.x = fmaxf(acc1.x + bb1.x, 0.f); acc1.y = fmaxf(acc1.y + bb1.y, 0.f);
    acc1.z = fmaxf(acc1.z + bb1.z, 0.f); acc1.w = fmaxf(acc1.w + bb1.w, 0.f);

    float4* op = (float4*)(out + (size_t)gw * 256);
    op[lane] = acc0;
    op[lane + 32] = acc1;
}

// ============================================================================
// layer-2 aggregation: one warp per dst node, single head, 2-way unroll.
// ============================================================================
__global__ __launch_bounds__(256) void aggregate_l2(
    const int* __restrict__ off, const int* __restrict__ csr,
    const float* __restrict__ as_, const float* __restrict__ ad_,
    const float* __restrict__ h, const float* __restrict__ b2,
    float* __restrict__ out, int n)
{
    int gw = (blockIdx.x * blockDim.x + threadIdx.x) >> 5;
    int lane = threadIdx.x & 31;
    if (gw >= n) return;
    int start = off[gw], end = off[gw + 1];

    float adn = ad_[gw];

    float ds = 0.f;
    for (int e = start + lane; e < end; e += 32) {
        int s = csr[e];
        ds += __expf(lrelu(as_[s] + adn));
    }
#pragma unroll
    for (int o = 16; o; o >>= 1) ds += __shfl_xor_sync(0xffffffffu, ds, o);
    float r = 1.f / (ds + 1e-16f);

    float4 acc = make_float4(0.f, 0.f, 0.f, 0.f);
    int e = start;
    for (; e + 2 <= end; e += 2) {
        int s0 = csr[e], s1 = csr[e + 1];
        float4 v0 = ((const float4*)(h + (size_t)s0 * OUTC))[lane];
        float4 v1 = ((const float4*)(h + (size_t)s1 * OUTC))[lane];
        float w0 = __expf(lrelu(as_[s0] + adn)) * r;
        float w1 = __expf(lrelu(as_[s1] + adn)) * r;
        acc.x += v0.x * w0 + v1.x * w1; acc.y += v0.y * w0 + v1.y * w1;
        acc.z += v0.z * w0 + v1.z * w1; acc.w += v0.w * w0 + v1.w * w1;
    }
    if (e < end) {
        int s0 = csr[e];
        float4 v0 = ((const float4*)(h + (size_t)s0 * OUTC))[lane];
        float w0 = __expf(lrelu(as_[s0] + adn)) * r;
        acc.x += v0.x * w0; acc.y += v0.y * w0;
        acc.z += v0.z * w0; acc.w += v0.w * w0;
    }

    float4 bb = ((const float4*)b2)[lane];
    acc.x += bb.x; acc.y += bb.y; acc.z += bb.z; acc.w += bb.w;
    ((float4*)(out + (size_t)gw * OUTC))[lane] = acc;
}

// ============================================================================
extern "C" void kernel_launch(void* const* d_in, const int* in_sizes, int n_in,
                              void* d_out, int out_size)
{
    const float* x      = (const float*)d_in[0];
    const int*   ei     = (const int*)  d_in[1];
    const float* W1     = (const float*)d_in[2];
    const float* a_src1 = (const float*)d_in[3];
    const float* a_dst1 = (const float*)d_in[4];
    const float* b1     = (const float*)d_in[5];
    const float* W2     = (const float*)d_in[6];
    const float* a_src2 = (const float*)d_in[7];
    const float* a_dst2 = (const float*)d_in[8];
    const float* b2     = (const float*)d_in[9];
    float* out = (float*)d_out;

    int n    = in_sizes[0] / INF_;   // 50000
    int E    = in_sizes[1] / 2;      // 800000
    int Etot = E + n;

    float *h1, *out1, *as1, *ad1, *h2, *as2, *ad2;
    int *cnt, *off, *part, *csr;
    cudaGetSymbolAddress((void**)&h1,  g_h1);
    cudaGetSymbolAddress((void**)&out1,g_out1);
    cudaGetSymbolAddress((void**)&as1, g_as1);
    cudaGetSymbolAddress((void**)&ad1, g_ad1);
    cudaGetSymbolAddress((void**)&h2,  g_h2);
    cudaGetSymbolAddress((void**)&as2, g_as2);
    cudaGetSymbolAddress((void**)&ad2, g_ad2);
    cudaGetSymbolAddress((void**)&cnt, g_cnt);
    cudaGetSymbolAddress((void**)&off, g_off);
    cudaGetSymbolAddress((void**)&part,g_part);
    cudaGetSymbolAddress((void**)&csr, g_csr);

    // side stream + fork/join events (created once; host-side handles only)
    static cudaStream_t sB = nullptr;
    static cudaEvent_t  evF = nullptr, evJ = nullptr;
    if (sB == nullptr) {
        cudaStreamCreateWithFlags(&sB, cudaStreamNonBlocking);
        cudaEventCreateWithFlags(&evF, cudaEventDisableTiming);
        cudaEventCreateWithFlags(&evJ, cudaEventDisableTiming);
    }

    const int T = 256;
    auto cdiv = [](int a, int b) { return (a + b - 1) / b; };
    int nchunks = cdiv(n, 1024);

    // ---- fork: CSR build on side stream, concurrent with GEMM1 + attn1 ----
    cudaEventRecord(evF, 0);
    cudaStreamWaitEvent(sB, evF, 0);

    cudaMemsetAsync(cnt, 0, (size_t)n * sizeof(int), sB);
    count_kernel<<<cdiv(Etot, T), T, 0, sB>>>(ei, E, Etot, cnt);
    scan1_kernel<<<nchunks, 1024, 0, sB>>>(cnt, off, part, n);
    scan_fix_kernel<<<nchunks, 1024, 0, sB>>>(off, cnt, part, n);
    scatter_kernel<<<cdiv(Etot, T), T, 0, sB>>>(ei, E, Etot, cnt, csr);
    cudaEventRecord(evJ, sB);

    // ---- main stream: layer-1 GEMM + attention coefficients ----
    {
        dim3 grid(cdiv(HEADS * HID, BN), cdiv(n, BM));
        gemm3x_kernel<<<grid, 256>>>(x, W1, h1, n, HEADS * HID, INF_);
    }
    attn_coef_l1<<<cdiv(n * HEADS, T), T>>>(h1, a_src1, a_dst1, as1, ad1, n);

    // ---- join: aggregation needs both CSR and attention coefficients ----
    cudaStreamWaitEvent(0, evJ, 0);
    aggregate_l1<<<cdiv(n * 32, T), T>>>(off, csr, as1, ad1, h1, b1, out1, n);

    // ---- layer 2 ----
    {
        dim3 grid(cdiv(OUTC, BN), cdiv(n, BM));
        gemm3x_kernel<<<grid, 256>>>(out1, W2, h2, n, OUTC, HEADS * HID);
    }
    attn_coef_l2<<<cdiv(n * 32, T), T>>>(h2, a_src2, a_dst2, as2, ad2, n);
    aggregate_l2<<<cdiv(n * 32, T), T>>>(off, csr, as2, ad2, h2, b2, out, n);
}